// round 15
// baseline (speedup 1.0000x reference)
#include <cuda_runtime.h>
#include <math.h>

// Problem constants
#define BS    4
#define CC    64
#define HH    128
#define WW    128
#define HW    (HH * WW)
#define NPIX  (BS * HW)        // 65536 pixels
#define NTOT  (NPIX * CC)      // 4194304 field elements
#define O2    128
#define DT    0.1f
#define THRESH 0.01
#define NSTEPS 50

// Geometry: 512-thread blocks, one warp owns 16 consecutive pixels
#define BLOCKS   256
#define THREADS  512
#define WARPS    16
#define PIXB     16

// SMEM layouts
#define W1P 132     // w1 rows [c][o 0..127], pitch 132 floats (528B, 16B-aligned)
#define W2P 68      // w2 rows [store-row][ch 0..63], pitch 68 (272B, 16B-aligned)
#define FHP 20      // f/h staging pitch (80B rows: 2-way worst-case on writes)
#define TP  68      // transpose region pitch (fcT/dT: [pix][ch])
#define REGION 2176 // floats/warp: f|h (64*20=1280, aliased) then fcT(1088)+dT(1088)
#define SMEM_FLOATS (CC * W1P + O2 * W2P + WARPS * REGION)
#define SMEM_BYTES  (SMEM_FLOATS * 4 + WARPS * 8)

// Persistent device state
__device__ float    g_f0[NTOT];
__device__ float    g_f1[NTOT];
__device__ int      g_done;
__device__ int      g_parity;
__device__ int      g_steps;
__device__ double   g_sum;
__device__ unsigned g_count;

__global__ void reset_kernel() {
    g_done = 0; g_parity = 0; g_steps = 0; g_sum = 0.0; g_count = 0u;
}

// NCHW -> NHWC
__global__ void nchw_to_nhwc(const float* __restrict__ in) {
    __shared__ float tile[32][33];
    int b  = blockIdx.z;
    int p0 = blockIdx.x * 32;
    int c0 = blockIdx.y * 32;
    const float* src = in   + (size_t)b * CC * HW;
    float*       dst = g_f0 + (size_t)b * HW * CC;
    for (int i = threadIdx.y; i < 32; i += 8)
        tile[i][threadIdx.x] = src[(size_t)(c0 + i) * HW + p0 + threadIdx.x];
    __syncthreads();
    for (int i = threadIdx.y; i < 32; i += 8)
        dst[(size_t)(p0 + i) * CC + c0 + threadIdx.x] = tile[threadIdx.x][i];
}

// NHWC (current parity) -> NCHW into d_out
__global__ void nhwc_to_nchw(float* __restrict__ out) {
    __shared__ float tile[32][33];
    const float* srcbuf = g_parity ? g_f1 : g_f0;
    int b  = blockIdx.z;
    int p0 = blockIdx.x * 32;
    int c0 = blockIdx.y * 32;
    const float* src = srcbuf + (size_t)b * HW * CC;
    float*       dst = out    + (size_t)b * CC * HW;
    for (int i = threadIdx.y; i < 32; i += 8)
        tile[i][threadIdx.x] = src[(size_t)(p0 + i) * CC + c0 + threadIdx.x];
    __syncthreads();
    for (int i = threadIdx.y; i < 32; i += 8)
        dst[(size_t)(c0 + i) * HW + p0 + threadIdx.x] = tile[threadIdx.x][i];
}

__global__ void write_steps(float* out, int out_size) {
    for (int i = NTOT; i < out_size; i++) out[i] = (float)g_steps;
}

__device__ __forceinline__ float gelu_exact(float v) {
    return 0.5f * v * (1.0f + erff(v * 0.70710678118654752440f));
}

// ---- packed f32x2 helpers (sm_103a FFMA2) ----
__device__ __forceinline__ unsigned long long dup2(float v) {
    unsigned long long r;
    asm("mov.b64 %0, {%1, %1};" : "=l"(r) : "f"(v));
    return r;
}
__device__ __forceinline__ void ffma2(unsigned long long& acc,
                                      unsigned long long a, unsigned long long b) {
    asm("fma.rn.f32x2 %0, %1, %2, %0;" : "+l"(acc) : "l"(a), "l"(b));
}
__device__ __forceinline__ void unpack2(unsigned long long v, float& lo, float& hi) {
    asm("mov.b64 {%0, %1}, %2;" : "=f"(lo), "=f"(hi) : "l"(v));
}
// 16B shared load -> two f32x2 operands
__device__ __forceinline__ void lds128_2x64(unsigned long long& a, unsigned long long& b,
                                            const float* p) {
    unsigned saddr = (unsigned)__cvta_generic_to_shared(p);
    asm volatile("ld.shared.v2.u64 {%0, %1}, [%2];" : "=l"(a), "=l"(b) : "r"(saddr));
}

// h storage-row map: out o = b*8+i lives at pass=i>>2, row=(i&3)*16+b
// Fused step: 16-pixel warp batch, half-warp pixel split, big register tiles.
__global__ __launch_bounds__(THREADS, 1)
void step_kernel(const float* __restrict__ dw, const float* __restrict__ db,
                 const float* __restrict__ w1, const float* __restrict__ b1,
                 const float* __restrict__ w2, const float* __restrict__ b2,
                 const float* __restrict__ dcoeff)
{
    if (g_done) return;

    extern __shared__ float smem[];
    float*  sW1  = smem;                          // [64][132]
    float*  sW2  = sW1 + CC * W1P;                // [128 store-rows][68]
    float*  sBuf = sW2 + O2 * W2P;                // [16 warps][REGION]
    double* sRed = (double*)(sBuf + WARPS * REGION);

    const float* src = g_parity ? g_f1 : g_f0;
    float*       dst = g_parity ? g_f0 : g_f1;

    int tid = threadIdx.x;

    // Stage W1: w1[o*64+c] -> sW1[c][o]
    for (int i = tid; i < CC * O2; i += THREADS) {
        int o = i >> 6, c = i & 63;
        sW1[c * W1P + o] = w1[i];
    }
    // Stage W2: w2[c*128+o] -> sW2[store_row(o)][c]
    for (int i = tid; i < CC * O2; i += THREADS) {
        int c = i >> 7, o = i & 127;
        int iq = o & 7, bq = o >> 3;
        int row = (iq >> 2) * 64 + (iq & 3) * 16 + bq;
        sW2[row * W2P + c] = w2[i];
    }
    __syncthreads();

    int lane = tid & 31, wid = tid >> 5;
    int blk = lane & 15;        // lane's output-block (GEMM1) / channel-block (GEMM2)
    int half = lane >> 4;       // lane's pixel half (pixels half*8 .. half*8+7)
    float* sFw = sBuf + wid * REGION;    // f/h rows [0..1279]
    float* fcT = sFw;                    // [16 pix][68]   (valid after GEMMs)
    float* dT  = sFw + 16 * TP;          // [16 pix][68]

    float dc = dcoeff[0];

    int p0 = blockIdx.x * (WARPS * PIXB) + wid * PIXB;
    int b  = p0 >> 14;
    int y  = (p0 >> 7) & 127;
    int x  = p0 & 127;                   // multiple of 16
    const float* base = src + (size_t)b * (HW * CC);
    int rowidx = (y * WW + x) << 6;

    // ---- Phase A: stage f[ch][pix] (lane owns channel rows lane, lane+32) ----
    {
        float v0[PIXB], v1[PIXB];
        #pragma unroll
        for (int p = 0; p < PIXB; p++) {
            int ci = rowidx + (p << 6);
            v0[p] = base[ci + lane];
            v1[p] = base[ci + 32 + lane];
        }
        float* r0 = sFw + lane * FHP;
        float* r1 = sFw + (lane + 32) * FHP;
        #pragma unroll
        for (int q = 0; q < 4; q++) {
            *(float4*)(r0 + 4 * q) = make_float4(v0[4*q], v0[4*q+1], v0[4*q+2], v0[4*q+3]);
            *(float4*)(r1 + 4 * q) = make_float4(v1[4*q], v1[4*q+1], v1[4*q+2], v1[4*q+3]);
        }
    }
    __syncwarp();

    // ---- Phase B: GEMM1, lane tile = 8 outputs (blk*8..+7) x 4 pairs (its half) ----
    unsigned long long acc1[8][4];
    {
        float4 b1lo = ((const float4*)b1)[blk * 2];
        float4 b1hi = ((const float4*)b1)[blk * 2 + 1];
        float bv[8] = {b1lo.x, b1lo.y, b1lo.z, b1lo.w, b1hi.x, b1hi.y, b1hi.z, b1hi.w};
        #pragma unroll
        for (int i = 0; i < 8; i++) {
            unsigned long long bb = dup2(bv[i]);
            #pragma unroll
            for (int q = 0; q < 4; q++) acc1[i][q] = bb;
        }
    }
    #pragma unroll 4
    for (int c = 0; c < CC; c++) {
        const float* wr = sW1 + c * W1P + blk * 8;
        float4 wa = *(const float4*)(wr);
        float4 wb = *(const float4*)(wr + 4);
        unsigned long long f0, f1, f2, f3;
        lds128_2x64(f0, f1, sFw + c * FHP + half * 8);
        lds128_2x64(f2, f3, sFw + c * FHP + half * 8 + 4);
        float wv[8] = {wa.x, wa.y, wa.z, wa.w, wb.x, wb.y, wb.z, wb.w};
        #pragma unroll
        for (int i = 0; i < 8; i++) {
            unsigned long long ai = dup2(wv[i]);
            ffma2(acc1[i][0], ai, f0);
            ffma2(acc1[i][1], ai, f1);
            ffma2(acc1[i][2], ai, f2);
            ffma2(acc1[i][3], ai, f3);
        }
    }
    __syncwarp();   // f reads complete before h overwrites the region

    // gelu + write h for a pass, then GEMM2 accumulate that pass
    unsigned long long acc2[4][4];
    {
        float4 b2v = ((const float4*)b2)[blk];
        float bv[4] = {b2v.x, b2v.y, b2v.z, b2v.w};
        #pragma unroll
        for (int j = 0; j < 4; j++) {
            unsigned long long bb = dup2(bv[j]);
            #pragma unroll
            for (int q = 0; q < 4; q++) acc2[j][q] = bb;
        }
    }

    #pragma unroll
    for (int pass = 0; pass < 2; pass++) {
        // write h rows for this pass: outs i = pass*4 .. pass*4+3
        #pragma unroll
        for (int il = 0; il < 4; il++) {
            int i = pass * 4 + il;
            float hv[8];
            #pragma unroll
            for (int q = 0; q < 4; q++) {
                float lo, hi; unpack2(acc1[i][q], lo, hi);
                hv[2 * q]     = gelu_exact(lo);
                hv[2 * q + 1] = gelu_exact(hi);
            }
            float* hr = sFw + (il * 16 + blk) * FHP + half * 8;
            *(float4*)(hr)     = make_float4(hv[0], hv[1], hv[2], hv[3]);
            *(float4*)(hr + 4) = make_float4(hv[4], hv[5], hv[6], hv[7]);
        }
        __syncwarp();

        // GEMM2 over this pass's 64 rows: lane tile = 4 ch (blk*4..+3) x 4 pairs
        #pragma unroll 4
        for (int r = 0; r < 64; r++) {
            float4 wv = *(const float4*)(sW2 + (pass * 64 + r) * W2P + blk * 4);
            unsigned long long h0, h1, h2, h3;
            lds128_2x64(h0, h1, sFw + r * FHP + half * 8);
            lds128_2x64(h2, h3, sFw + r * FHP + half * 8 + 4);
            float wj[4] = {wv.x, wv.y, wv.z, wv.w};
            #pragma unroll
            for (int j = 0; j < 4; j++) {
                unsigned long long aj = dup2(wj[j]);
                ffma2(acc2[j][0], aj, h0);
                ffma2(acc2[j][1], aj, h1);
                ffma2(acc2[j][2], aj, h2);
                ffma2(acc2[j][3], aj, h3);
            }
        }
        __syncwarp();   // pass's h reads done before next pass overwrites rows
    }

    // ---- Phase D: depthwise conv (lane owns ch {lane, lane+32}) + transpose ----
    float dwr0[9], dwr1[9];
    #pragma unroll
    for (int k = 0; k < 9; k++) {
        dwr0[k] = dw[lane * 9 + k];
        dwr1[k] = dw[(lane + 32) * 9 + k];
    }
    float dbr0 = db[lane], dbr1 = db[lane + 32];

    float d0[PIXB], d1[PIXB];
    #pragma unroll
    for (int i = 0; i < PIXB; i++) { d0[i] = dbr0; d1[i] = dbr1; }

    #pragma unroll
    for (int r = 0; r < 3; r++) {
        int yy = y + r - 1;
        bool rowok = (unsigned)yy < HH;
        #pragma unroll
        for (int cc = 0; cc < 18; cc++) {
            int xx = x + cc - 1;
            float v0 = 0.0f, v1 = 0.0f;
            if (rowok && (unsigned)xx < WW) {
                int ni = (yy * WW + xx) << 6;
                v0 = base[ni + lane];
                v1 = base[ni + 32 + lane];
            }
            if (r == 1 && cc >= 1 && cc <= 16) {   // center row: stash fc transposed
                int pi = cc - 1;
                fcT[pi * TP + lane]      = v0;
                fcT[pi * TP + lane + 32] = v1;
            }
            int plo = cc - 2 < 0 ? 0 : cc - 2;
            int phi = cc > 15 ? 15 : cc;
            #pragma unroll
            for (int pi = plo; pi <= phi; pi++) {
                int k = r * 3 + (cc - pi);
                d0[pi] = fmaf(dwr0[k], v0, d0[pi]);
                d1[pi] = fmaf(dwr1[k], v1, d1[pi]);
            }
        }
    }
    // stash d transposed: [pix][ch]
    #pragma unroll
    for (int p = 0; p < PIXB; p++) {
        dT[p * TP + lane]      = d0[p];
        dT[p * TP + lane + 32] = d1[p];
    }
    __syncwarp();

    // ---- Phase E: Euler update, coalesced STG.128 over lane's 4 channels ----
    float asum = 0.0f;
    float* dbase = dst + (size_t)b * (HW * CC);
    #pragma unroll
    for (int pl = 0; pl < 8; pl++) {
        int p  = half * 8 + pl;               // pixel within batch
        int pp = pl >> 1, hf = pl & 1;
        float4 fc = *(const float4*)(fcT + p * TP + 4 * blk);
        float4 dd = *(const float4*)(dT  + p * TP + 4 * blk);
        float rj[4];
        #pragma unroll
        for (int j = 0; j < 4; j++) {
            float lo, hi; unpack2(acc2[j][pp], lo, hi);
            rj[j] = hf ? hi : lo;
        }
        float4 n;
        n.x = fc.x + DT * fmaf(dc, dd.x, rj[0]);
        n.y = fc.y + DT * fmaf(dc, dd.y, rj[1]);
        n.z = fc.z + DT * fmaf(dc, dd.z, rj[2]);
        n.w = fc.w + DT * fmaf(dc, dd.w, rj[3]);
        *(float4*)(dbase + rowidx + (p << 6) + 4 * blk) = n;
        asum += fabsf(n.x - fc.x) + fabsf(n.y - fc.y)
              + fabsf(n.z - fc.z) + fabsf(n.w - fc.w);
    }

    // ---- Reduction + fused finalize in last block ----
    #pragma unroll
    for (int off = 16; off; off >>= 1)
        asum += __shfl_xor_sync(0xffffffffu, asum, off);
    if (lane == 0) sRed[wid] = (double)asum;
    __syncthreads();
    if (tid == 0) {
        double s = 0.0;
        #pragma unroll
        for (int i = 0; i < WARPS; i++) s += sRed[i];
        atomicAdd(&g_sum, s);
        __threadfence();
        unsigned t = atomicInc(&g_count, BLOCKS - 1);
        if (t == BLOCKS - 1) {
            double change = *((volatile double*)&g_sum) * (1.0 / (double)NTOT);
            g_steps += 1;
            g_parity ^= 1;
            if (change < THRESH) g_done = 1;
            g_sum = 0.0;
        }
    }
}

extern "C" void kernel_launch(void* const* d_in, const int* in_sizes, int n_in,
                              void* d_out, int out_size) {
    const float* field  = (const float*)d_in[0];
    const float* dw     = (const float*)d_in[1];
    const float* db     = (const float*)d_in[2];
    const float* w1     = (const float*)d_in[3];
    const float* b1     = (const float*)d_in[4];
    const float* w2     = (const float*)d_in[5];
    const float* b2     = (const float*)d_in[6];
    const float* dcoeff = (const float*)d_in[7];

    cudaFuncSetAttribute(step_kernel,
                         cudaFuncAttributeMaxDynamicSharedMemorySize, SMEM_BYTES);

    reset_kernel<<<1, 1>>>();

    dim3 tb(32, 8), tg(HW / 32, CC / 32, BS);
    nchw_to_nhwc<<<tg, tb>>>(field);

    for (int s = 0; s < NSTEPS; s++)
        step_kernel<<<BLOCKS, THREADS, SMEM_BYTES>>>(dw, db, w1, b1, w2, b2, dcoeff);

    nhwc_to_nchw<<<tg, tb>>>((float*)d_out);
    write_steps<<<1, 1>>>((float*)d_out, out_size);
}